// round 17
// baseline (speedup 1.0000x reference)
#include <cuda_runtime.h>
#include <cuda_bf16.h>

#define NGRID   10000
#define NSTEPS  730
#define LENF    15
#define NEARZEROF 1e-5f
#define UNR     5

__device__ __forceinline__ float fast_lg2(float x) {
    float r; asm("lg2.approx.f32 %0, %1;" : "=f"(r) : "f"(x)); return r;
}
__device__ __forceinline__ float fast_ex2(float x) {
    float r; asm("ex2.approx.f32 %0, %1;" : "=f"(r) : "f"(x)); return r;
}

// ---------------------------------------------------------------------------
// Fused HBV scan + gamma routing. One thread per cell, single launch.
// 15-step macro tiles -> compile-time circular-buffer slots for routing.
// ---------------------------------------------------------------------------
__global__ __launch_bounds__(64, 1)
void hbv_fused_kernel(const float* __restrict__ x_phy,   // [NSTEPS, NGRID, 3]
                      const float* __restrict__ phy,     // [NGRID, 16]
                      float* __restrict__ out)           // [NSTEPS, NGRID]
{
    int g = blockIdx.x * blockDim.x + threadIdx.x;
    if (g >= NGRID) return;

    const float* ps = phy + g * 16;
    float BETA   = ps[0]  * 5.0f   + 1.0f;
    float FC     = ps[1]  * 950.0f + 50.0f;
    float K0     = ps[2]  * 0.85f  + 0.05f;
    float K1     = ps[3]  * 0.49f  + 0.01f;
    float K2     = ps[4]  * 0.199f + 0.001f;
    float LP     = ps[5]  * 0.8f   + 0.2f;
    float PERC   = ps[6]  * 10.0f;
    float UZL    = ps[7]  * 100.0f;
    float TT     = ps[8]  * 5.0f   - 2.5f;
    float CFMAX  = ps[9]  * 9.5f   + 0.5f;
    float CFR    = ps[10] * 0.1f;
    float CWH    = ps[11] * 0.2f;
    float BETAET = ps[12] * 4.7f   + 0.3f;
    float C      = ps[13];
    float aa     = fmaxf(ps[14] * 2.9f, 0.0f) + 0.1f;
    float theta  = fmaxf(ps[15] * 6.5f, 0.0f) + 0.5f;

    float invFC     = 1.0f / FC;
    float invLPFC   = 1.0f / (LP * FC);
    float nCFRCFMAX = -(CFR * CFMAX);        // rpot = max(nCFRCFMAX*d, 0)
    float CA = BETA   * fast_lg2(invFC);     // folded pow constants
    float CE = BETAET * fast_lg2(invLPFC);
    float omK0  = 1.0f - K0;
    float omK1  = 1.0f - K1;
    float omK2  = 1.0f - K2;
    float K0UZL = K0 * UZL;

    // ---- routing weights (gammaln & a*log(theta) cancel under norm) ----
    const float LOGTG[LENF] = {
        -0.69314718f, 0.40546511f, 0.91629073f, 1.25276297f, 1.50407740f,
         1.70474809f, 1.87180218f, 2.01490302f, 2.14006616f, 2.25129180f,
         2.35137526f, 2.44234704f, 2.52572864f, 2.60268969f, 2.67418505f };
    float invTheta = 1.0f / theta;
    float am1 = aa - 1.0f;
    float w[LENF];
    float wsum = 0.0f;
#pragma unroll
    for (int k = 0; k < LENF; k++) {
        float tg = (float)k + 0.5f;
        float e = expf(fmaf(am1, LOGTG[k], -tg * invTheta));
        w[k] = e;
        wsum += e;
    }
    float invw = 1.0f / wsum;
#pragma unroll
    for (int k = 0; k < LENF; k++) w[k] *= invw;

    // ---- state ----
    float snow = NEARZEROF, melt = NEARZEROF, sm = NEARZEROF,
          suz = NEARZEROF, slz = NEARZEROF;
    float cslz    = C * slz;
    float om_kcap = fmaf(-cslz, invFC, 1.0f);

    // circular history: hist[t % 15] = q_t; q_{t<0} = 0
    float hist[LENF];
#pragma unroll
    for (int k = 0; k < LENF; k++) hist[k] = 0.0f;

    const int rowstride = NGRID * 3;
    const float* xbase = x_phy + (size_t)g * 3;
    float* ocol = out + g;

    float Ap[UNR], Atm[UNR], Ape[UNR];
    float Bp[UNR], Btm[UNR], Bpe[UNR];
    float Cp[UNR], Ctm[UNR], Cpe[UNR];

#define LOADG(P, T, E, GRP)                                             \
    _Pragma("unroll")                                                   \
    for (int u = 0; u < UNR; u++) {                                     \
        int idx = (GRP) * UNR + u;                                      \
        if (idx >= NSTEPS) idx = NSTEPS - 1;                            \
        const float* xn = xbase + (size_t)idx * rowstride;              \
        P[u] = __ldg(xn + 0); T[u] = __ldg(xn + 1); E[u] = __ldg(xn + 2); \
    }

// 5 steps; PH = compile-time phase (0,5,10) -> all hist indices static.
#define STEPS(P, T, E, BASE, PH)                                        \
    _Pragma("unroll")                                                   \
    for (int u = 0; u < UNR; u++) {                                     \
        float p  = P[u];                                                \
        float tm = T[u];                                                \
        float pe = E[u];                                                \
        /* input-only precomputes (shared d; independent selects) */    \
        float d      = tm - TT;                                         \
        float rain   = (d >= 0.0f) ? p : 0.0f;                          \
        float snowf  = (d >= 0.0f) ? 0.0f : p;                          \
        float mpot   = fmaxf(CFMAX * d, 0.0f);                          \
        float rpot   = fmaxf(nCFRCFMAX * d, 0.0f);                      \
        /* pow #1 (MUFU shadow filled by snow chain + routing) */       \
        float soil_wet = fminf(fast_ex2(fmaf(BETA, fast_lg2(sm), CA)), 1.0f); \
        /* snow bucket (min-form) */                                    \
        float sp     = snow + snowf;                                    \
        float m      = fminf(mpot, sp);                                 \
        float snow1  = sp - m;                                          \
        float melt1  = melt + m;                                        \
        float refr   = fminf(rpot, melt1);                              \
        float melt2  = melt1 - refr;                                    \
        snow         = snow1 + refr;                                    \
        float tosoil = fmaxf(fmaf(-CWH, snow, melt2), 0.0f);            \
        melt         = melt2 - tosoil;                                  \
        /* soil bucket: recharge/excess folded into rex = smrt - sm_c */ \
        float rt     = rain + tosoil;                                   \
        float smrt   = sm + rt;                                         \
        float sm_pre = fmaf(-rt, soil_wet, smrt);                       \
        float sm_c   = fminf(sm_pre, FC);                               \
        float rex    = smrt - sm_c;     /* == recharge + excess */      \
        float evapfac = fminf(fast_ex2(fmaf(BETAET, fast_lg2(sm_pre), CE)), 1.0f); \
        float sm_et  = fmaxf(fmaf(-pe, evapfac, sm_c), NEARZEROF);      \
        float sm_a   = fmaf(sm_et, om_kcap, cslz);                      \
        float sm_b   = sm_et + slz;                                     \
        sm           = fminf(sm_a, sm_b);                               \
        slz          = fmaxf(sm_b - sm, NEARZEROF);  /* slz - cap */    \
        /* response (condensed; percact parallel to suz2) */            \
        float suz1    = suz + rex;                                      \
        float suz2    = fmaxf(suz1 - PERC, 0.0f);                       \
        float percact = fminf(suz1, PERC);                              \
        float suz3    = fminf(suz2, fmaf(omK0, suz2, K0UZL));           \
        suz           = omK1 * suz3;                                    \
        float slz1    = slz + percact;                                  \
        slz           = omK2 * slz1;                                    \
        float q       = (suz2 - suz) + (slz1 - slz);                    \
        /* next-step capillary coefficients (off-chain) */              \
        cslz    = C * slz;                                              \
        om_kcap = fmaf(-cslz, invFC, 1.0f);                             \
        /* fused routing: compile-time circular indices */              \
        hist[((PH) + u) % LENF] = q;                                    \
        float qr = 0.0f;                                                \
        _Pragma("unroll")                                               \
        for (int k = 0; k < LENF; k++)                                  \
            qr = fmaf(w[k], hist[((PH) + u - k + LENF) % LENF], qr);    \
        ocol[(size_t)((BASE) + u) * NGRID] = qr;                        \
    }

    // prologue: groups 0,1,2
    LOADG(Ap, Atm, Ape, 0)
    LOADG(Bp, Btm, Bpe, 1)
    LOADG(Cp, Ctm, Cpe, 2)

    // 48 macro tiles of 15 steps (groups 3m, 3m+1, 3m+2)
    for (int mt = 0; mt < 48; mt++) {
        int base = mt * 15;
        int grp  = mt * 3;
        STEPS(Ap, Atm, Ape, base,      0)
        LOADG(Ap, Atm, Ape, grp + 3)
        STEPS(Bp, Btm, Bpe, base + 5,  5)
        LOADG(Bp, Btm, Bpe, grp + 4)
        STEPS(Cp, Ctm, Cpe, base + 10, 10)
        LOADG(Cp, Ctm, Cpe, grp + 5)
    }
    // tail: steps 720..729; 720 % 15 == 0 -> phases 0 and 5
    STEPS(Ap, Atm, Ape, 720, 0)
    STEPS(Bp, Btm, Bpe, 725, 5)

#undef LOADG
#undef STEPS
}

extern "C" void kernel_launch(void* const* d_in, const int* in_sizes, int n_in,
                              void* d_out, int out_size) {
    const float* x_phy = (const float*)d_in[0];
    const float* phy   = (const float*)d_in[1];
    float* out         = (float*)d_out;
    (void)in_sizes; (void)n_in; (void)out_size;

    // 1 cell/thread, 64-thread blocks -> 157 blocks over 148 SMs
    hbv_fused_kernel<<<(NGRID + 63) / 64, 64>>>(x_phy, phy, out);
}